// round 11
// baseline (speedup 1.0000x reference)
#include <cuda_runtime.h>
#include <cuda_bf16.h>
#include <cuda_fp8.h>
#include <cstdint>

// Energy-distance loss, FP8 QMMA f32-acc at the legacy-tensor ceiling.
//   loss = mean_b[ mean||x-y|| - 0.5 mean||x-x'|| - 0.5 mean||y-y'|| ]
// R11 = R10 + 296-CTA balanced job split (perfect 2/SM) + finalize fused
// into dist via last-CTA completion counter + streaming loads in prep.

#define NPTS  512
#define DIMS  128
#define NB    128
#define NROWS 65536
#define N_CROSS_CTAS 2048
#define N_SELF_CTAS  1280
#define N_JOBS (N_CROSS_CTAS + 2 * N_SELF_CTAS)   // 4608
#define N_CTAS 296                                 // 2 per SM, all resident
// 4608 = 168*16 + 128*15

__device__ uint8_t g_fx[NROWS * DIMS];   // e4m3
__device__ uint8_t g_fy[NROWS * DIMS];
__device__ float g_norm_x[NROWS];
__device__ float g_norm_y[NROWS];
__device__ float g_partials[N_JOBS];
__device__ unsigned g_done;              // zero-init; reset by last CTA

// smem layout (bytes from 1024-aligned base)
#define OFF_A    0        // 16 KB fp8 tile, 128B rows, xor-swizzled
#define OFF_B    16384
#define OFF_NX   32768
#define OFF_NY   33280
#define OFF_RED  33792
#define SMEM_REQ (1024 + 33824)

__device__ __forceinline__ uint32_t smem_u32(const void* p) {
    uint32_t a;
    asm("{ .reg .u64 t; cvta.to.shared.u64 t, %1; cvt.u32.u64 %0, t; }"
        : "=r"(a) : "l"(p));
    return a;
}

// ---------------------------------------------------------------------------
// Kernel 0: fp32 -> e4m3 convert + exact fp32 squared norms. 8 rows/warp.
// Streaming (evict-first) loads: X/Y are read exactly once; keep L2 for fp8.
// ---------------------------------------------------------------------------
__global__ void prep_kernel(const float* __restrict__ X,
                            const float* __restrict__ Y) {
    int warp = (blockIdx.x * blockDim.x + threadIdx.x) >> 5;
    int lane = threadIdx.x & 31;
    int row8 = warp * 8;
    const float* src; uint8_t* dst; float* ndst; int r0;
    if (row8 < NROWS) { src = X; dst = g_fx; ndst = g_norm_x; r0 = row8; }
    else              { src = Y; dst = g_fy; ndst = g_norm_y; r0 = row8 - NROWS; }

    float4 v[8];
    float s[8];
#pragma unroll
    for (int k = 0; k < 8; k++) {
        v[k] = __ldcs(((const float4*)(src + (size_t)(r0 + k) * DIMS)) + lane);
        s[k] = v[k].x * v[k].x + v[k].y * v[k].y + v[k].z * v[k].z + v[k].w * v[k].w;
    }
#pragma unroll
    for (int k = 0; k < 8; k++) {
        float2 lo = make_float2(v[k].x, v[k].y);
        float2 hi = make_float2(v[k].z, v[k].w);
        unsigned p0 = __nv_cvt_float2_to_fp8x2(lo, __NV_SATFINITE, __NV_E4M3);
        unsigned p1 = __nv_cvt_float2_to_fp8x2(hi, __NV_SATFINITE, __NV_E4M3);
        *(unsigned*)(dst + (size_t)(r0 + k) * DIMS + lane * 4) =
            (p0 & 0xffffu) | (p1 << 16);
#pragma unroll
        for (int o = 16; o; o >>= 1) s[k] += __shfl_xor_sync(0xffffffffu, s[k], o);
        if (lane == 0) ndst[r0 + k] = s[k];
    }
}

// ---------------------------------------------------------------------------
// Kernel 1: 128x128 distance tiles via e4m3 QMMA + fused finalize.
// 296 CTAs, contiguous 16/15 job ranges. 8 warps in 4(m) x 2(n).
// ---------------------------------------------------------------------------
__global__ __launch_bounds__(256, 2)
void dist_kernel(float* __restrict__ out) {
    extern __shared__ char dyn_smem[];
    char* sm = (char*)((((uintptr_t)dyn_smem) + 1023) & ~(uintptr_t)1023);
    uint32_t sbase = smem_u32(sm);

    int tid  = threadIdx.x;
    int lane = tid & 31;
    int warp = tid >> 5;
    int wm   = warp >> 1;
    int wn   = warp & 1;

    int a_r = (lane & 7) + ((lane >> 3) & 1) * 8;
    int a_u = lane >> 4;
    int b_r = (lane & 7) + ((lane >> 4) << 3);
    int b_u = (lane >> 3) & 1;

    // contiguous job range: first 168 CTAs get 16 jobs, rest 15
    int cta = blockIdx.x;
    int j0 = (cta < 168) ? cta * 16 : 168 * 16 + (cta - 168) * 15;
    int j1 = j0 + ((cta < 168) ? 16 : 15);

    const uint8_t* prevAbase = (const uint8_t*)0;

    for (int job = j0; job < j1; job++) {
        // ---- job decode ----
        const uint8_t *Ap, *Bp;
        const float *nAp, *nBp;
        int b, tr, tc;
        bool selfm;
        if (job < N_CROSS_CTAS) {
            b = job >> 4;
            int t = job & 15;
            tr = t >> 2; tc = t & 3;
            Ap = g_fx; Bp = g_fy; nAp = g_norm_x; nBp = g_norm_y;
            selfm = false;
        } else {
            int r = job - N_CROSS_CTAS;
            int isY = (r >= N_SELF_CTAS);
            if (isY) r -= N_SELF_CTAS;
            b = r / 10;
            int t = r - b * 10;
            int trr = 0, tt = t;
            while (tt >= 4 - trr) { tt -= 4 - trr; trr++; }
            tr = trr; tc = trr + tt;
            Ap = isY ? g_fy : g_fx;
            Bp = Ap;
            nAp = isY ? g_norm_y : g_norm_x;
            nBp = nAp;
            selfm = true;
        }
        bool diag = selfm && (tr == tc);
        const uint8_t* Abase = Ap + ((size_t)b * NPTS + tr * 128) * DIMS;
        const uint8_t* Bbase = Bp + ((size_t)b * NPTS + tc * 128) * DIMS;
        bool reuseA = (Abase == prevAbase);
        prevAbase = Abase;

        // ---- stage via cp.async (prev job's reduction barrier licenses) ----
#pragma unroll
        for (int q = 0; q < 4; q++) {
            int idx = tid + q * 256;
            int r = idx >> 3, u = idx & 7;
            int soff = r * 128 + ((u ^ (r & 7)) << 4);
            asm volatile("cp.async.cg.shared.global [%0], [%1], 16;"
                         :: "r"(sbase + OFF_B + soff),
                            "l"((const void*)(Bbase + (size_t)r * DIMS + u * 16)));
            if (!reuseA)
                asm volatile("cp.async.cg.shared.global [%0], [%1], 16;"
                             :: "r"(sbase + OFF_A + soff),
                                "l"((const void*)(Abase + (size_t)r * DIMS + u * 16)));
        }
        if (tid < 128) {
            if (!reuseA)
                *(float*)(sm + OFF_NX + tid * 4) = nAp[b * NPTS + tr * 128 + tid];
        } else {
            *(float*)(sm + OFF_NY + (tid - 128) * 4) = nBp[b * NPTS + tc * 128 + tid - 128];
        }
        asm volatile("cp.async.commit_group;");
        asm volatile("cp.async.wait_group 0;" ::: "memory");
        __syncthreads();

        float tsum = 0.f;

        // Diagonal tiles: warps fully below the diagonal skip everything.
        bool skip = diag && (wn == 0) && (wm >= 2);
        if (!skip) {
            // ---- mainloop: 4 k32 chunks, f32 accumulators ----
            float acc[2][8][4];
#pragma unroll
            for (int mt = 0; mt < 2; mt++)
#pragma unroll
                for (int nt = 0; nt < 8; nt++)
#pragma unroll
                    for (int c = 0; c < 4; c++) acc[mt][nt][c] = 0.f;

            uint32_t sA = sbase + OFF_A;
            uint32_t sB = sbase + OFF_B;

#pragma unroll
            for (int kk = 0; kk < 4; kk++) {
                unsigned af[2][4];
#pragma unroll
                for (int mt = 0; mt < 2; mt++) {
                    int r = wm * 32 + mt * 16 + a_r;
                    int u = kk * 2 + a_u;
                    unsigned addr = sA + (unsigned)(r * 128 + ((u ^ (r & 7)) << 4));
                    asm volatile(
                        "ldmatrix.sync.aligned.m8n8.x4.shared.b16 {%0,%1,%2,%3}, [%4];"
                        : "=r"(af[mt][0]), "=r"(af[mt][1]), "=r"(af[mt][2]), "=r"(af[mt][3])
                        : "r"(addr));
                }
#pragma unroll
                for (int pp = 0; pp < 4; pp++) {
                    int r = wn * 64 + pp * 16 + b_r;
                    int u = kk * 2 + b_u;
                    unsigned addr = sB + (unsigned)(r * 128 + ((u ^ (r & 7)) << 4));
                    unsigned bf[4];
                    asm volatile(
                        "ldmatrix.sync.aligned.m8n8.x4.shared.b16 {%0,%1,%2,%3}, [%4];"
                        : "=r"(bf[0]), "=r"(bf[1]), "=r"(bf[2]), "=r"(bf[3])
                        : "r"(addr));
#pragma unroll
                    for (int mt = 0; mt < 2; mt++) {
                        asm volatile(
                            "mma.sync.aligned.m16n8k32.row.col.f32.e4m3.e4m3.f32 "
                            "{%0,%1,%2,%3}, {%4,%5,%6,%7}, {%8,%9}, {%0,%1,%2,%3};"
                            : "+f"(acc[mt][2*pp][0]), "+f"(acc[mt][2*pp][1]),
                              "+f"(acc[mt][2*pp][2]), "+f"(acc[mt][2*pp][3])
                            : "r"(af[mt][0]), "r"(af[mt][1]), "r"(af[mt][2]), "r"(af[mt][3]),
                              "r"(bf[0]), "r"(bf[1]));
                        asm volatile(
                            "mma.sync.aligned.m16n8k32.row.col.f32.e4m3.e4m3.f32 "
                            "{%0,%1,%2,%3}, {%4,%5,%6,%7}, {%8,%9}, {%0,%1,%2,%3};"
                            : "+f"(acc[mt][2*pp+1][0]), "+f"(acc[mt][2*pp+1][1]),
                              "+f"(acc[mt][2*pp+1][2]), "+f"(acc[mt][2*pp+1][3])
                            : "r"(af[mt][0]), "r"(af[mt][1]), "r"(af[mt][2]), "r"(af[mt][3]),
                              "r"(bf[2]), "r"(bf[3]));
                    }
                }
            }

            // ---- epilogue ----
            int g  = lane >> 2;
            int ct = lane & 3;

            float nx[2][2];
#pragma unroll
            for (int mt = 0; mt < 2; mt++) {
                int r0 = wm * 32 + mt * 16 + g;
                nx[mt][0] = *(const float*)(sm + OFF_NX + r0 * 4);
                nx[mt][1] = *(const float*)(sm + OFF_NX + (r0 + 8) * 4);
            }
            float ny[8][2];
#pragma unroll
            for (int nt = 0; nt < 8; nt++) {
                int c0 = wn * 64 + nt * 8 + 2 * ct;
                ny[nt][0] = *(const float*)(sm + OFF_NY + c0 * 4);
                ny[nt][1] = *(const float*)(sm + OFF_NY + (c0 + 1) * 4);
            }

            float ts0 = 0.f, ts1 = 0.f;
            if (diag) {
#pragma unroll
                for (int mt = 0; mt < 2; mt++)
#pragma unroll
                    for (int nt = 0; nt < 8; nt++)
#pragma unroll
                        for (int c = 0; c < 4; c++) {
                            int ri = c >> 1, cj = c & 1;
                            int irow = wm * 32 + mt * 16 + g + ri * 8;
                            int jcol = wn * 64 + nt * 8 + 2 * ct + cj;
                            float d2 = fmaf(acc[mt][nt][c], -2.f, nx[mt][ri]) + ny[nt][cj];
                            d2 = fmaxf(d2, 0.f);
                            float dd;
                            asm("sqrt.approx.f32 %0, %1;" : "=f"(dd) : "f"(d2));
                            if (jcol <= irow) dd = 0.f;
                            if (c & 1) ts1 += dd; else ts0 += dd;
                        }
            } else {
#pragma unroll
                for (int mt = 0; mt < 2; mt++)
#pragma unroll
                    for (int nt = 0; nt < 8; nt++)
#pragma unroll
                        for (int c = 0; c < 4; c++) {
                            float d2 = fmaf(acc[mt][nt][c], -2.f, nx[mt][c >> 1]) + ny[nt][c & 1];
                            d2 = fmaxf(d2, 0.f);
                            float dd;
                            asm("sqrt.approx.f32 %0, %1;" : "=f"(dd) : "f"(d2));
                            if (c & 1) ts1 += dd; else ts0 += dd;
                        }
            }
            tsum = ts0 + ts1;
#pragma unroll
            for (int o = 16; o; o >>= 1) tsum += __shfl_xor_sync(0xffffffffu, tsum, o);
        }

        if (lane == 0) *(float*)(sm + OFF_RED + warp * 4) = tsum;
        __syncthreads();     // licenses smem overwrite by next job
        if (tid == 0) {
            float s = 0.f;
#pragma unroll
            for (int w = 0; w < 8; w++) s += *(float*)(sm + OFF_RED + w * 4);
            g_partials[job] = s;
        }
    }

    // ---- fused finalize: last CTA to finish reduces all partials ----
    __threadfence();
    __shared__ unsigned s_last;
    if (tid == 0) {
        unsigned ticket = atomicAdd(&g_done, 1u);
        s_last = (ticket == N_CTAS - 1) ? 1u : 0u;
    }
    __syncthreads();
    if (s_last) {
        __threadfence();    // acquire all g_partials writes
        __shared__ double sd[256];
        double s = 0.0;
        for (int i = tid; i < N_JOBS; i += 256) {
            double v = (double)g_partials[i];
            s += (i < N_CROSS_CTAS) ? v : -v;
        }
        sd[tid] = s;
        __syncthreads();
        for (int o = 128; o; o >>= 1) {
            if (tid < o) sd[tid] += sd[tid + o];
            __syncthreads();
        }
        if (tid == 0) {
            out[0] = (float)(sd[0] / ((double)NB * NPTS * NPTS));
            g_done = 0;     // reset for next graph replay
        }
    }
}

// ---------------------------------------------------------------------------
extern "C" void kernel_launch(void* const* d_in, const int* in_sizes, int n_in,
                              void* d_out, int out_size) {
    const float* X = (const float*)d_in[0];
    const float* Y = (const float*)d_in[1];

    cudaFuncSetAttribute(dist_kernel,
                         cudaFuncAttributeMaxDynamicSharedMemorySize, SMEM_REQ);

    prep_kernel<<<2048, 256>>>(X, Y);
    dist_kernel<<<N_CTAS, 256, SMEM_REQ>>>((float*)d_out);
}

// round 12
// speedup vs baseline: 1.0900x; 1.0900x over previous
#include <cuda_runtime.h>
#include <cuda_bf16.h>
#include <cuda_fp8.h>
#include <cstdint>

// Energy-distance loss, FP8 QMMA f32-acc.
//   loss = mean_b[ mean||x-y|| - 0.5 mean||x-x'|| - 0.5 mean||y-y'|| ]
// R12: issue-slot diet. ncu showed dist is issue/latency-bound (tensor 33.8%,
// alu 31.6%, occ 22%). Changes: XOR-folded ldmatrix addresses (precomputed
// once), precomputed staging offsets, cross-job per-lane signed accumulation
// (one shfl-reduce per kernel instead of per job), fmaxf dropped (diag mask
// zeroes the only possibly-negative d2 after sqrt).

#define NPTS  512
#define DIMS  128
#define NB    128
#define NROWS 65536
#define N_CROSS_CTAS 2048
#define N_SELF_CTAS  1280
#define N_JOBS (N_CROSS_CTAS + 2 * N_SELF_CTAS)   // 4608
#define N_CTAS 296                                 // 2 per SM
// 4608 = 168*16 + 128*15

__device__ uint8_t g_fx[NROWS * DIMS];   // e4m3
__device__ uint8_t g_fy[NROWS * DIMS];
__device__ float g_norm_x[NROWS];
__device__ float g_norm_y[NROWS];
__device__ float g_partials[N_CTAS * 8]; // signed per-warp totals
__device__ unsigned g_done;              // zero-init; reset by last CTA

// smem layout (bytes from 1024-aligned base)
#define OFF_A    0        // 16 KB fp8 tile, 128B rows, xor-swizzled
#define OFF_B    16384
#define OFF_NX   32768
#define OFF_NY   33280
#define SMEM_REQ (1024 + 33792)

__device__ __forceinline__ uint32_t smem_u32(const void* p) {
    uint32_t a;
    asm("{ .reg .u64 t; cvta.to.shared.u64 t, %1; cvt.u32.u64 %0, t; }"
        : "=r"(a) : "l"(p));
    return a;
}

// ---------------------------------------------------------------------------
// Kernel 0: fp32 -> e4m3 convert + exact fp32 squared norms. 8 rows/warp.
// ---------------------------------------------------------------------------
__global__ void prep_kernel(const float* __restrict__ X,
                            const float* __restrict__ Y) {
    int warp = (blockIdx.x * blockDim.x + threadIdx.x) >> 5;
    int lane = threadIdx.x & 31;
    int row8 = warp * 8;
    const float* src; uint8_t* dst; float* ndst; int r0;
    if (row8 < NROWS) { src = X; dst = g_fx; ndst = g_norm_x; r0 = row8; }
    else              { src = Y; dst = g_fy; ndst = g_norm_y; r0 = row8 - NROWS; }

    float4 v[8];
    float s[8];
#pragma unroll
    for (int k = 0; k < 8; k++) {
        v[k] = __ldcs(((const float4*)(src + (size_t)(r0 + k) * DIMS)) + lane);
        s[k] = v[k].x * v[k].x + v[k].y * v[k].y + v[k].z * v[k].z + v[k].w * v[k].w;
    }
#pragma unroll
    for (int k = 0; k < 8; k++) {
        float2 lo = make_float2(v[k].x, v[k].y);
        float2 hi = make_float2(v[k].z, v[k].w);
        unsigned p0 = __nv_cvt_float2_to_fp8x2(lo, __NV_SATFINITE, __NV_E4M3);
        unsigned p1 = __nv_cvt_float2_to_fp8x2(hi, __NV_SATFINITE, __NV_E4M3);
        *(unsigned*)(dst + (size_t)(r0 + k) * DIMS + lane * 4) =
            (p0 & 0xffffu) | (p1 << 16);
#pragma unroll
        for (int o = 16; o; o >>= 1) s[k] += __shfl_xor_sync(0xffffffffu, s[k], o);
        if (lane == 0) ndst[r0 + k] = s[k];
    }
}

// ---------------------------------------------------------------------------
// Kernel 1: 128x128 distance tiles via e4m3 QMMA + fused finalize.
// ---------------------------------------------------------------------------
__global__ __launch_bounds__(256, 2)
void dist_kernel(float* __restrict__ out) {
    extern __shared__ char dyn_smem[];
    char* sm = (char*)((((uintptr_t)dyn_smem) + 1023) & ~(uintptr_t)1023);
    uint32_t sbase = smem_u32(sm);

    int tid  = threadIdx.x;
    int lane = tid & 31;
    int warp = tid >> 5;
    int wm   = warp >> 1;
    int wn   = warp & 1;
    int g    = lane >> 2;
    int ct   = lane & 3;

    // ---- per-thread constants, computed ONCE ----
    // ldmatrix bases with swizzle folded in: addr(kk) = base ^ (kk<<5)
    int a_r = (lane & 7) + ((lane >> 3) & 1) * 8;
    int a_u = lane >> 4;
    int b_r = (lane & 7) + ((lane >> 4) << 3);
    int b_u = (lane >> 3) & 1;

    uint32_t A_base[2], B_base[4];
#pragma unroll
    for (int mt = 0; mt < 2; mt++) {
        int r = wm * 32 + mt * 16 + a_r;
        int s = r & 7;
        A_base[mt] = sbase + OFF_A + r * 128
                   + (((a_u ^ (s & 1)) | (s & 6)) << 4);
    }
#pragma unroll
    for (int pp = 0; pp < 4; pp++) {
        int r = wn * 64 + pp * 16 + b_r;
        int s = r & 7;
        B_base[pp] = sbase + OFF_B + r * 128
                   + (((b_u ^ (s & 1)) | (s & 6)) << 4);
    }

    // staging offsets (thread-constant across jobs)
    int st_soff[4], st_goff[4];
#pragma unroll
    for (int q = 0; q < 4; q++) {
        int idx = tid + q * 256;
        int r = idx >> 3, u = idx & 7;
        st_soff[q] = r * 128 + ((u ^ (r & 7)) << 4);
        st_goff[q] = r * DIMS + u * 16;
    }

    // contiguous job range: first 168 CTAs get 16 jobs, rest 15
    int cta = blockIdx.x;
    int j0 = (cta < 168) ? cta * 16 : 168 * 16 + (cta - 168) * 15;
    int j1 = j0 + ((cta < 168) ? 16 : 15);

    const uint8_t* prevAbase = (const uint8_t*)0;
    float tot0 = 0.f, tot1 = 0.f, tot2 = 0.f, tot3 = 0.f;  // signed, cross jobs

    for (int job = j0; job < j1; job++) {
        // ---- job decode ----
        const uint8_t *Ap, *Bp;
        const float *nAp, *nBp;
        int b, tr, tc;
        bool selfm;
        if (job < N_CROSS_CTAS) {
            b = job >> 4;
            int t = job & 15;
            tr = t >> 2; tc = t & 3;
            Ap = g_fx; Bp = g_fy; nAp = g_norm_x; nBp = g_norm_y;
            selfm = false;
        } else {
            int r = job - N_CROSS_CTAS;
            int isY = (r >= N_SELF_CTAS);
            if (isY) r -= N_SELF_CTAS;
            b = r / 10;
            int t = r - b * 10;
            int trr = 0, tt = t;
            while (tt >= 4 - trr) { tt -= 4 - trr; trr++; }
            tr = trr; tc = trr + tt;
            Ap = isY ? g_fy : g_fx;
            Bp = Ap;
            nAp = isY ? g_norm_y : g_norm_x;
            nBp = nAp;
            selfm = true;
        }
        bool diag = selfm && (tr == tc);
        const uint8_t* Abase = Ap + ((size_t)b * NPTS + tr * 128) * DIMS;
        const uint8_t* Bbase = Bp + ((size_t)b * NPTS + tc * 128) * DIMS;
        bool reuseA = (Abase == prevAbase);
        prevAbase = Abase;

        // ---- stage via cp.async (prev job's trailing barrier licenses) ----
#pragma unroll
        for (int q = 0; q < 4; q++) {
            asm volatile("cp.async.cg.shared.global [%0], [%1], 16;"
                         :: "r"(sbase + OFF_B + st_soff[q]),
                            "l"((const void*)(Bbase + st_goff[q])));
            if (!reuseA)
                asm volatile("cp.async.cg.shared.global [%0], [%1], 16;"
                             :: "r"(sbase + OFF_A + st_soff[q]),
                                "l"((const void*)(Abase + st_goff[q])));
        }
        if (tid < 128) {
            if (!reuseA)
                *(float*)(sm + OFF_NX + tid * 4) = nAp[b * NPTS + tr * 128 + tid];
        } else {
            *(float*)(sm + OFF_NY + (tid - 128) * 4) = nBp[b * NPTS + tc * 128 + tid - 128];
        }
        asm volatile("cp.async.commit_group;");
        asm volatile("cp.async.wait_group 0;" ::: "memory");
        __syncthreads();

        // Diagonal tiles: warps fully below the diagonal skip everything.
        bool skip = diag && (wn == 0) && (wm >= 2);
        if (!skip) {
            // ---- mainloop: 4 k32 chunks, f32 accumulators ----
            float acc[2][8][4];
#pragma unroll
            for (int mt = 0; mt < 2; mt++)
#pragma unroll
                for (int nt = 0; nt < 8; nt++)
#pragma unroll
                    for (int c = 0; c < 4; c++) acc[mt][nt][c] = 0.f;

#pragma unroll
            for (int kk = 0; kk < 4; kk++) {
                unsigned af[2][4];
#pragma unroll
                for (int mt = 0; mt < 2; mt++) {
                    unsigned addr = A_base[mt] ^ (unsigned)(kk << 5);
                    asm volatile(
                        "ldmatrix.sync.aligned.m8n8.x4.shared.b16 {%0,%1,%2,%3}, [%4];"
                        : "=r"(af[mt][0]), "=r"(af[mt][1]), "=r"(af[mt][2]), "=r"(af[mt][3])
                        : "r"(addr));
                }
#pragma unroll
                for (int pp = 0; pp < 4; pp++) {
                    unsigned addr = B_base[pp] ^ (unsigned)(kk << 5);
                    unsigned bf[4];
                    asm volatile(
                        "ldmatrix.sync.aligned.m8n8.x4.shared.b16 {%0,%1,%2,%3}, [%4];"
                        : "=r"(bf[0]), "=r"(bf[1]), "=r"(bf[2]), "=r"(bf[3])
                        : "r"(addr));
#pragma unroll
                    for (int mt = 0; mt < 2; mt++) {
                        asm volatile(
                            "mma.sync.aligned.m16n8k32.row.col.f32.e4m3.e4m3.f32 "
                            "{%0,%1,%2,%3}, {%4,%5,%6,%7}, {%8,%9}, {%0,%1,%2,%3};"
                            : "+f"(acc[mt][2*pp][0]), "+f"(acc[mt][2*pp][1]),
                              "+f"(acc[mt][2*pp][2]), "+f"(acc[mt][2*pp][3])
                            : "r"(af[mt][0]), "r"(af[mt][1]), "r"(af[mt][2]), "r"(af[mt][3]),
                              "r"(bf[0]), "r"(bf[1]));
                        asm volatile(
                            "mma.sync.aligned.m16n8k32.row.col.f32.e4m3.e4m3.f32 "
                            "{%0,%1,%2,%3}, {%4,%5,%6,%7}, {%8,%9}, {%0,%1,%2,%3};"
                            : "+f"(acc[mt][2*pp+1][0]), "+f"(acc[mt][2*pp+1][1]),
                              "+f"(acc[mt][2*pp+1][2]), "+f"(acc[mt][2*pp+1][3])
                            : "r"(af[mt][0]), "r"(af[mt][1]), "r"(af[mt][2]), "r"(af[mt][3]),
                              "r"(bf[2]), "r"(bf[3]));
                    }
                }
            }

            // ---- epilogue: d = sqrt(nx + ny - 2*dot); no clamp (see header) ----
            float nx[2][2];
#pragma unroll
            for (int mt = 0; mt < 2; mt++) {
                int r0 = wm * 32 + mt * 16 + g;
                nx[mt][0] = *(const float*)(sm + OFF_NX + r0 * 4);
                nx[mt][1] = *(const float*)(sm + OFF_NX + (r0 + 8) * 4);
            }
            float ny[8][2];
#pragma unroll
            for (int nt = 0; nt < 8; nt++) {
                int c0 = wn * 64 + nt * 8 + 2 * ct;
                ny[nt][0] = *(const float*)(sm + OFF_NY + c0 * 4);
                ny[nt][1] = *(const float*)(sm + OFF_NY + (c0 + 1) * 4);
            }

            float ts0 = 0.f, ts1 = 0.f, ts2 = 0.f, ts3 = 0.f;
            if (diag) {
#pragma unroll
                for (int mt = 0; mt < 2; mt++)
#pragma unroll
                    for (int nt = 0; nt < 8; nt++)
#pragma unroll
                        for (int c = 0; c < 4; c++) {
                            int ri = c >> 1, cj = c & 1;
                            int irow = wm * 32 + mt * 16 + g + ri * 8;
                            int jcol = wn * 64 + nt * 8 + 2 * ct + cj;
                            float d2 = fmaf(acc[mt][nt][c], -2.f, nx[mt][ri]) + ny[nt][cj];
                            float dd;
                            asm("sqrt.approx.f32 %0, %1;" : "=f"(dd) : "f"(d2));
                            if (jcol <= irow) dd = 0.f;   // also kills NaN at i==j
                            if      (c == 0) ts0 += dd;
                            else if (c == 1) ts1 += dd;
                            else if (c == 2) ts2 += dd;
                            else             ts3 += dd;
                        }
            } else {
#pragma unroll
                for (int mt = 0; mt < 2; mt++)
#pragma unroll
                    for (int nt = 0; nt < 8; nt++)
#pragma unroll
                        for (int c = 0; c < 4; c++) {
                            float d2 = fmaf(acc[mt][nt][c], -2.f, nx[mt][c >> 1]) + ny[nt][c & 1];
                            float dd;
                            asm("sqrt.approx.f32 %0, %1;" : "=f"(dd) : "f"(d2));
                            if      (c == 0) ts0 += dd;
                            else if (c == 1) ts1 += dd;
                            else if (c == 2) ts2 += dd;
                            else             ts3 += dd;
                        }
            }
            if (selfm) { tot0 -= ts0; tot1 -= ts1; tot2 -= ts2; tot3 -= ts3; }
            else       { tot0 += ts0; tot1 += ts1; tot2 += ts2; tot3 += ts3; }
        }

        __syncthreads();     // licenses smem overwrite by next job
    }

    // ---- single per-warp reduction + write ----
    float tsum = (tot0 + tot1) + (tot2 + tot3);
#pragma unroll
    for (int o = 16; o; o >>= 1) tsum += __shfl_xor_sync(0xffffffffu, tsum, o);
    if (lane == 0) g_partials[cta * 8 + warp] = tsum;

    // ---- fused finalize: last CTA reduces all signed partials ----
    __threadfence();
    __shared__ unsigned s_last;
    if (tid == 0) {
        unsigned ticket = atomicAdd(&g_done, 1u);
        s_last = (ticket == N_CTAS - 1) ? 1u : 0u;
    }
    __syncthreads();
    if (s_last) {
        __threadfence();
        __shared__ double sd[256];
        double s = 0.0;
        for (int i = tid; i < N_CTAS * 8; i += 256)
            s += (double)g_partials[i];
        sd[tid] = s;
        __syncthreads();
        for (int o = 128; o; o >>= 1) {
            if (tid < o) sd[tid] += sd[tid + o];
            __syncthreads();
        }
        if (tid == 0) {
            out[0] = (float)(sd[0] / ((double)NB * NPTS * NPTS));
            g_done = 0;     // reset for next graph replay
        }
    }
}

// ---------------------------------------------------------------------------
extern "C" void kernel_launch(void* const* d_in, const int* in_sizes, int n_in,
                              void* d_out, int out_size) {
    const float* X = (const float*)d_in[0];
    const float* Y = (const float*)d_in[1];

    cudaFuncSetAttribute(dist_kernel,
                         cudaFuncAttributeMaxDynamicSharedMemorySize, SMEM_REQ);

    prep_kernel<<<2048, 256>>>(X, Y);
    dist_kernel<<<N_CTAS, 256, SMEM_REQ>>>((float*)d_out);
}